// round 8
// baseline (speedup 1.0000x reference)
#include <cuda_runtime.h>
#include <math.h>
#include <stdint.h>

#define NN   32768
#define EE   1048576
#define NSD  64
#define NVD  32
#define LATD 256

// ---- scales ----
#define INV8    0.125f                 // 1/sqrt(64)
#define C1      0.10206207261596575f   // (1/sqrt(3))/sqrt(32) = 1/sqrt(96)
#define INV_R2  0.7071067811865476f
#define INVS32  0.17677669529663687f   // 1/sqrt(32)
#define S_USS   0.011048543456039806f  // 1/(64*sqrt(2))
#define S_UVV   0.012757998811063534f  // 1/(32*sqrt(6))
#define S_V     0.015625f              // 1/sqrt(64*32*2) = 1/64

typedef unsigned long long ull;

// ---- scratch (device globals; no allocation) ----
__device__ float g_ns[NN * NSD];
__device__ float g_nv[NN * NVD * 3];
__device__ float g_NF[(size_t)NN * 384];  // SS(64)|Q(3x64)|SV(32)|VS(3x32)
__device__ float g_as[NN * NSD];
__device__ float g_av[NN * NVD * 3];

__device__ __forceinline__ float sigmf(float x) { return 1.0f / (1.0f + __expf(-x)); }

// ---- packed f32x2 helpers ----
__device__ __forceinline__ void ffma2(ull& d, ull a, ull b) {
    asm("fma.rn.f32x2 %0, %1, %2, %0;" : "+l"(d) : "l"(a), "l"(b));
}
__device__ __forceinline__ ull fmul2(ull a, ull b) {
    ull r; asm("mul.rn.f32x2 %0, %1, %2;" : "=l"(r) : "l"(a), "l"(b)); return r;
}
__device__ __forceinline__ ull fadd2(ull a, ull b) {
    ull r; asm("add.rn.f32x2 %0, %1, %2;" : "=l"(r) : "l"(a), "l"(b)); return r;
}
__device__ __forceinline__ ull pack2(float x, float y) {
    ull r;
    asm("mov.b64 %0, {%1, %2};" : "=l"(r)
        : "r"(__float_as_uint(x)), "r"(__float_as_uint(y)));
    return r;
}
__device__ __forceinline__ float2 unpack2(ull v) {
    unsigned int lo, hi;
    asm("mov.b64 {%0, %1}, %2;" : "=r"(lo), "=r"(hi) : "l"(v));
    return make_float2(__uint_as_float(lo), __uint_as_float(hi));
}

// ============================ k_in: ns = x @ W_in / 8 ============================
__global__ __launch_bounds__(256) void k_in(const float* __restrict__ x,
                                            const float* __restrict__ Win) {
    __shared__ float xs[32 * 65];
    __shared__ float ws[64 * 64];
    const int tid = threadIdx.x;
    const int node0 = blockIdx.x * 32;
    const float4* wg = (const float4*)Win;
    float4* ws4 = (float4*)ws;
#pragma unroll
    for (int r = 0; r < 4; r++) ws4[tid + r * 256] = wg[tid + r * 256];
#pragma unroll
    for (int r = 0; r < 8; r++) {
        int lin = tid + r * 256; int t = lin >> 6, i = lin & 63;
        xs[t * 65 + i] = x[(size_t)(node0 + t) * 64 + i];
    }
    __syncthreads();
    const int o = tid & 63, tq = tid >> 6;
    float acc[8] = {0, 0, 0, 0, 0, 0, 0, 0};
#pragma unroll 16
    for (int i = 0; i < 64; i++) {
        float w = ws[i * 64 + o];
#pragma unroll
        for (int tt = 0; tt < 8; tt++) acc[tt] += xs[(tq * 8 + tt) * 65 + i] * w;
    }
#pragma unroll
    for (int tt = 0; tt < 8; tt++)
        g_ns[(size_t)(node0 + tq * 8 + tt) * 64 + o] = acc[tt] * INV8;
}

// ============== k_feat: per-node precompute SS, Q, SV, VS ==============
__global__ __launch_bounds__(256) void k_feat(const float* __restrict__ Wss,
                                              const float* __restrict__ Wvv0,
                                              const float* __restrict__ Wsv,
                                              const float* __restrict__ Wvs) {
    __shared__ float s_wss[64 * 64];
    __shared__ float s_wvv[32 * 64];
    __shared__ float s_wsv[64 * 32];
    __shared__ float s_wvs[32 * 32];
    __shared__ float s_ns[8][64];
    __shared__ float s_nv[8][96];
    const int tid = threadIdx.x;
    for (int i = tid; i < 4096; i += 256) s_wss[i] = Wss[i];
    for (int i = tid; i < 2048; i += 256) s_wvv[i] = Wvv0[i];
    for (int i = tid; i < 2048; i += 256) s_wsv[i] = Wsv[i];
    for (int i = tid; i < 1024; i += 256) s_wvs[i] = Wvs[i];
    const int w = tid >> 5, lane = tid & 31;
    const int node = blockIdx.x * 8 + w;
#pragma unroll
    for (int r = 0; r < 2; r++) s_ns[w][lane + 32 * r] = g_ns[(size_t)node * 64 + lane + 32 * r];
#pragma unroll
    for (int r = 0; r < 3; r++) s_nv[w][lane + 32 * r] = g_nv[(size_t)node * 96 + lane + 32 * r];
    __syncthreads();
    float* nf = g_NF + (size_t)node * 384;
#pragma unroll
    for (int h = 0; h < 2; h++) {
        int o = lane + 32 * h;
        float a = 0;
#pragma unroll 8
        for (int i = 0; i < 64; i++) a += s_ns[w][i] * s_wss[i * 64 + o];
        nf[o] = a;
    }
#pragma unroll
    for (int xx = 0; xx < 3; xx++) {
#pragma unroll
        for (int h = 0; h < 2; h++) {
            int o = lane + 32 * h;
            float a = 0;
#pragma unroll 8
            for (int m = 0; m < 32; m++) a += s_nv[w][m * 3 + xx] * s_wvv[m * 64 + o];
            nf[64 + xx * 64 + o] = a;
        }
    }
    {
        float a = 0;
#pragma unroll 8
        for (int i = 0; i < 64; i++) a += s_ns[w][i] * s_wsv[i * 32 + lane];
        nf[256 + lane] = a;
    }
#pragma unroll
    for (int xx = 0; xx < 3; xx++) {
        float a = 0;
#pragma unroll 8
        for (int m = 0; m < 32; m++) a += s_nv[w][m * 3 + xx] * s_wvs[m * 32 + lane];
        nf[288 + xx * 32 + lane] = a;
    }
}

// ================= k_edge: per-edge message + gate + scatter-add =================
__global__ __launch_bounds__(256) void k_edge(const float* __restrict__ eattr,
                                              const int* __restrict__ eidx,
                                              const float* __restrict__ gmw,
                                              const float* __restrict__ gmb) {
    __shared__ float s_gw[96], s_gb[96];
    const int tid = threadIdx.x;
    if (tid < 96) { s_gw[tid] = gmw[tid]; s_gb[tid] = gmb[tid]; }
    __syncthreads();
    const int w = tid >> 5, lane = tid & 31;
    const int e = blockIdx.x * 8 + w;
    const int r = eidx[e];
    const int c = eidx[EE + e];
    const float ev0 = eattr[(size_t)e * 4 + 0];
    const float ev1 = eattr[(size_t)e * 4 + 1];
    const float ev2 = eattr[(size_t)e * 4 + 2];
    const float es  = eattr[(size_t)e * 4 + 3];
    const float* nf = g_NF + (size_t)c * 384;
    float ms[2];
#pragma unroll
    for (int h = 0; h < 2; h++) {
        int o = lane + 32 * h;
        float dot = ev0 * nf[64 + o] + ev1 * nf[128 + o] + ev2 * nf[192 + o];
        float v = (es * nf[o] * INV8 + dot * C1) * INV_R2;
        ms[h] = v * sigmf(v);
    }
    const float sv = nf[256 + lane];
    float mv0 = (sv * ev0 * INV8 + es * nf[288 + lane] * INVS32) * INV_R2;
    float mv1 = (sv * ev1 * INV8 + es * nf[320 + lane] * INVS32) * INV_R2;
    float mv2 = (sv * ev2 * INV8 + es * nf[352 + lane] * INVS32) * INV_R2;
    float p = mv0 + mv1 + mv2;
#pragma unroll
    for (int off = 16; off; off >>= 1) p += __shfl_xor_sync(0xffffffffu, p, off);
    const float mean = p * (1.0f / 96.0f);
    const float g0 = sigmf(mean * s_gw[lane * 3 + 0] + s_gb[lane * 3 + 0]);
    const float g1 = sigmf(mean * s_gw[lane * 3 + 1] + s_gb[lane * 3 + 1]);
    const float g2 = sigmf(mean * s_gw[lane * 3 + 2] + s_gb[lane * 3 + 2]);
    float* as = g_as + (size_t)r * 64;
    float* av = g_av + (size_t)r * 96;
    atomicAdd(as + lane,        ms[0]);
    atomicAdd(as + lane + 32,   ms[1]);
    atomicAdd(av + lane * 3 + 0, mv0 * g0);
    atomicAdd(av + lane * 3 + 1, mv1 * g1);
    atomicAdd(av + lane * 3 + 2, mv2 * g2);
}

// ====== k_bilin: four bilinears + gate + residual ======
// 32 nodes / block, 256 threads, 2 blocks/SM.
// f32x2 accumulators pair consecutive nodes; W pre-duplicated in smem;
// node features stored TRANSPOSED so node pairs are contiguous (f32x2 A-gen).
// smem floats: ns_T 2048 | as_T 2048 | nv_T 3072 | av_T 3072 | W_s 8192 | A_s 6144
#define BILIN_SMEM (24576 * 4)

__global__ __launch_bounds__(256, 2) void k_bilin(const float* __restrict__ Wuss,
                                                  const float* __restrict__ Wuvv,
                                                  const float* __restrict__ Wusv,
                                                  const float* __restrict__ Wuvs,
                                                  const float* __restrict__ guw,
                                                  const float* __restrict__ gub) {
    extern __shared__ float sm[];
    float* ns_T = sm;                 // [64 feat][32 node]
    float* as_T = sm + 2048;          // [64][32]
    float* nv_T = sm + 4096;          // [96 feat(m*3+x)][32]
    float* av_T = sm + 7168;          // [96][32]
    float* W_s  = sm + 10240;         // A: [64kk][128 dup] ; B: [64kk][64 dup]
    float* A_s  = sm + 18432;         // A: [64kk][32] ; B: [3][64kk][32]
    const int tid = threadIdx.x;
    const int node0 = blockIdx.x * 32;

    // ---- transposed node-data loads (coalesced global reads, scattered STS) ----
    {
        const float4* gns = (const float4*)(g_ns + (size_t)node0 * 64);
        const float4* gas = (const float4*)(g_as + (size_t)node0 * 64);
#pragma unroll
        for (int r = 0; r < 2; r++) {
            int s = tid + r * 256;           // 512 float4
            int t = s >> 4, c = (s & 15) * 4;
            float4 v = gns[s], u = gas[s];
            ns_T[(c + 0) * 32 + t] = v.x; ns_T[(c + 1) * 32 + t] = v.y;
            ns_T[(c + 2) * 32 + t] = v.z; ns_T[(c + 3) * 32 + t] = v.w;
            as_T[(c + 0) * 32 + t] = u.x; as_T[(c + 1) * 32 + t] = u.y;
            as_T[(c + 2) * 32 + t] = u.z; as_T[(c + 3) * 32 + t] = u.w;
        }
        const float4* gnv = (const float4*)(g_nv + (size_t)node0 * 96);
        const float4* gav = (const float4*)(g_av + (size_t)node0 * 96);
#pragma unroll
        for (int r = 0; r < 3; r++) {
            int s = tid + r * 256;           // 768 float4
            int t = s / 24, c = (s % 24) * 4;
            float4 v = gnv[s], u = gav[s];
            nv_T[(c + 0) * 32 + t] = v.x; nv_T[(c + 1) * 32 + t] = v.y;
            nv_T[(c + 2) * 32 + t] = v.z; nv_T[(c + 3) * 32 + t] = v.w;
            av_T[(c + 0) * 32 + t] = u.x; av_T[(c + 1) * 32 + t] = u.y;
            av_T[(c + 2) * 32 + t] = u.z; av_T[(c + 3) * 32 + t] = u.w;
        }
    }
    __syncthreads();

    // ================ Phase A: u_s = uss + uvv ================
    // acc[p][o]: p = pair (2py+p), o = out (2tx+o); f32x2 lanes = node pair
    const int tx = tid & 31;   // out group: outs 2tx, 2tx+1
    const int py = tid >> 5;   // pair group: pairs 2py,2py+1 (nodes 4py..4py+3)
    ull a00 = 0, a01 = 0, a10 = 0, a11 = 0;
    const ull Suss2 = pack2(S_USS, S_USS);
    const ull Suvv2 = pack2(S_UVV, S_UVV);

    // --- uss: K=4096, k=(i<<6)|j ---
    for (int kb = 0; kb < 4096; kb += 64) {
        const float4* wg = (const float4*)(Wuss + (size_t)kb * 64);
#pragma unroll
        for (int r = 0; r < 4; r++) {
            int s = tid + r * 256;           // 1024 float4
            int kk = s >> 4, c = s & 15;
            float4 w = wg[s];
            float4* d = (float4*)(W_s + kk * 128 + c * 8);
            d[0] = make_float4(w.x, w.x, w.y, w.y);
            d[1] = make_float4(w.z, w.z, w.w, w.w);
        }
#pragma unroll
        for (int r = 0; r < 4; r++) {
            int lin = tid + r * 256;         // 1024 pairs
            int kk = lin >> 4, p = lin & 15;
            int k = kb + kk; int i = k >> 6, j = k & 63;
            ull na = *(const ull*)(ns_T + i * 32 + 2 * p);
            ull aa = *(const ull*)(as_T + j * 32 + 2 * p);
            *(ull*)(A_s + kk * 32 + 2 * p) = fmul2(fmul2(na, aa), Suss2);
        }
        __syncthreads();
#pragma unroll 16
        for (int kk = 0; kk < 64; kk++) {
            ulonglong2 a2 = *(const ulonglong2*)(A_s + kk * 32 + py * 4);
            ulonglong2 w2 = *(const ulonglong2*)(W_s + kk * 128 + tx * 4);
            ffma2(a00, a2.x, w2.x); ffma2(a01, a2.x, w2.y);
            ffma2(a10, a2.y, w2.x); ffma2(a11, a2.y, w2.y);
        }
        __syncthreads();
    }
    // --- uvv: K=3*1024, k=(m<<5)|n per x ---
    for (int kb = 0; kb < 3072; kb += 64) {
        int xx = kb >> 10, km = kb & 1023;
        const float4* wg = (const float4*)(Wuvv + (size_t)km * 64);
#pragma unroll
        for (int r = 0; r < 4; r++) {
            int s = tid + r * 256;
            int kk = s >> 4, c = s & 15;
            float4 w = wg[s];
            float4* d = (float4*)(W_s + kk * 128 + c * 8);
            d[0] = make_float4(w.x, w.x, w.y, w.y);
            d[1] = make_float4(w.z, w.z, w.w, w.w);
        }
#pragma unroll
        for (int r = 0; r < 4; r++) {
            int lin = tid + r * 256;
            int kk = lin >> 4, p = lin & 15;
            int k = km + kk; int m = k >> 5, n = k & 31;
            ull na = *(const ull*)(nv_T + (m * 3 + xx) * 32 + 2 * p);
            ull aa = *(const ull*)(av_T + (n * 3 + xx) * 32 + 2 * p);
            *(ull*)(A_s + kk * 32 + 2 * p) = fmul2(fmul2(na, aa), Suvv2);
        }
        __syncthreads();
#pragma unroll 16
        for (int kk = 0; kk < 64; kk++) {
            ulonglong2 a2 = *(const ulonglong2*)(A_s + kk * 32 + py * 4);
            ulonglong2 w2 = *(const ulonglong2*)(W_s + kk * 128 + tx * 4);
            ffma2(a00, a2.x, w2.x); ffma2(a01, a2.x, w2.y);
            ffma2(a10, a2.y, w2.x); ffma2(a11, a2.y, w2.y);
        }
        __syncthreads();
    }
    // u_s epilogue: silu + residual (ns_T stays intact for phase B)
    {
        ull accs[4] = {a00, a01, a10, a11};
#pragma unroll
        for (int p = 0; p < 2; p++) {
#pragma unroll
            for (int o = 0; o < 2; o++) {
                float2 u = unpack2(accs[p * 2 + o]);
                int og = 2 * tx + o;
                int tl = 4 * py + 2 * p;
                float s0 = u.x * sigmf(u.x);
                float s1 = u.y * sigmf(u.y);
                g_ns[(size_t)(node0 + tl) * 64 + og]     = ns_T[og * 32 + tl] + s0;
                g_ns[(size_t)(node0 + tl + 1) * 64 + og] = ns_T[og * 32 + tl + 1] + s1;
            }
        }
    }

    // ================ Phase B: u_v = usv + uvs ================
    // acc[x][o]: pair pb (nodes 2pb,2pb+1), outs 2ob,2ob+1, 3 x-components
    const int ob = tid & 15;   // outs 2ob, 2ob+1
    const int pb = tid >> 4;   // pair pb
    ull v00 = 0, v01 = 0, v10 = 0, v11 = 0, v20 = 0, v21 = 0;
    const ull Sv2 = pack2(S_V, S_V);

    // --- usv: K=2048 per x, k=(i<<5)|n ---
    for (int kb = 0; kb < 2048; kb += 64) {
        const float4* wg = (const float4*)(Wusv + (size_t)kb * 32);
#pragma unroll
        for (int r = 0; r < 2; r++) {
            int s = tid + r * 256;           // 512 float4
            int kk = s >> 3, c = s & 7;
            float4 w = wg[s];
            float4* d = (float4*)(W_s + kk * 64 + c * 8);
            d[0] = make_float4(w.x, w.x, w.y, w.y);
            d[1] = make_float4(w.z, w.z, w.w, w.w);
        }
#pragma unroll
        for (int r = 0; r < 12; r++) {
            int lin = tid + r * 256;         // 3072 pairs
            int xx = lin >> 10; int rem = lin & 1023;
            int kk = rem >> 4, p = rem & 15;
            int k = kb + kk; int i = k >> 5, n = k & 31;
            ull na = *(const ull*)(ns_T + i * 32 + 2 * p);
            ull va = *(const ull*)(av_T + (n * 3 + xx) * 32 + 2 * p);
            *(ull*)(A_s + xx * 2048 + kk * 32 + 2 * p) = fmul2(fmul2(na, va), Sv2);
        }
        __syncthreads();
#pragma unroll 8
        for (int kk = 0; kk < 64; kk++) {
            ulonglong2 w2 = *(const ulonglong2*)(W_s + kk * 64 + ob * 4);
            ull b0 = *(const ull*)(A_s + kk * 32 + pb * 2);
            ull b1 = *(const ull*)(A_s + 2048 + kk * 32 + pb * 2);
            ull b2 = *(const ull*)(A_s + 4096 + kk * 32 + pb * 2);
            ffma2(v00, b0, w2.x); ffma2(v01, b0, w2.y);
            ffma2(v10, b1, w2.x); ffma2(v11, b1, w2.y);
            ffma2(v20, b2, w2.x); ffma2(v21, b2, w2.y);
        }
        __syncthreads();
    }
    // --- uvs: K=2048 per x, k=(m<<6)|j ---
    for (int kb = 0; kb < 2048; kb += 64) {
        const float4* wg = (const float4*)(Wuvs + (size_t)kb * 32);
#pragma unroll
        for (int r = 0; r < 2; r++) {
            int s = tid + r * 256;
            int kk = s >> 3, c = s & 7;
            float4 w = wg[s];
            float4* d = (float4*)(W_s + kk * 64 + c * 8);
            d[0] = make_float4(w.x, w.x, w.y, w.y);
            d[1] = make_float4(w.z, w.z, w.w, w.w);
        }
#pragma unroll
        for (int r = 0; r < 12; r++) {
            int lin = tid + r * 256;
            int xx = lin >> 10; int rem = lin & 1023;
            int kk = rem >> 4, p = rem & 15;
            int k = kb + kk; int m = k >> 6, j = k & 63;
            ull na = *(const ull*)(nv_T + (m * 3 + xx) * 32 + 2 * p);
            ull aa = *(const ull*)(as_T + j * 32 + 2 * p);
            *(ull*)(A_s + xx * 2048 + kk * 32 + 2 * p) = fmul2(fmul2(na, aa), Sv2);
        }
        __syncthreads();
#pragma unroll 8
        for (int kk = 0; kk < 64; kk++) {
            ulonglong2 w2 = *(const ulonglong2*)(W_s + kk * 64 + ob * 4);
            ull b0 = *(const ull*)(A_s + kk * 32 + pb * 2);
            ull b1 = *(const ull*)(A_s + 2048 + kk * 32 + pb * 2);
            ull b2 = *(const ull*)(A_s + 4096 + kk * 32 + pb * 2);
            ffma2(v00, b0, w2.x); ffma2(v01, b0, w2.y);
            ffma2(v10, b1, w2.x); ffma2(v11, b1, w2.y);
            ffma2(v20, b2, w2.x); ffma2(v21, b2, w2.y);
        }
        __syncthreads();
    }

    // u_v epilogue: mean over 96 per node (16 threads share pair pb), gate, residual
    {
        ull psum = fadd2(fadd2(fadd2(v00, v01), fadd2(v10, v11)), fadd2(v20, v21));
        psum = fadd2(psum, __shfl_xor_sync(0xffffffffu, psum, 1));
        psum = fadd2(psum, __shfl_xor_sync(0xffffffffu, psum, 2));
        psum = fadd2(psum, __shfl_xor_sync(0xffffffffu, psum, 4));
        psum = fadd2(psum, __shfl_xor_sync(0xffffffffu, psum, 8));
        float2 pm = unpack2(psum);
        const float mean0 = pm.x * (1.0f / 96.0f);
        const float mean1 = pm.y * (1.0f / 96.0f);
        ull vacc[3][2] = {{v00, v01}, {v10, v11}, {v20, v21}};
        const int n0 = 2 * pb;
#pragma unroll
        for (int xx = 0; xx < 3; xx++) {
#pragma unroll
            for (int o = 0; o < 2; o++) {
                int f = (2 * ob + o) * 3 + xx;
                float gw = __ldg(guw + f), gb = __ldg(gub + f);
                float2 u = unpack2(vacc[xx][o]);
                float g0 = sigmf(mean0 * gw + gb);
                float g1 = sigmf(mean1 * gw + gb);
                g_nv[(size_t)(node0 + n0) * 96 + f]     = nv_T[f * 32 + n0] + u.x * g0;
                g_nv[(size_t)(node0 + n0 + 1) * 96 + f] = nv_T[f * 32 + n0 + 1] + u.y * g1;
            }
        }
    }
}

// ============================ k_out: out = ns @ W_out / 8 ============================
__global__ __launch_bounds__(256) void k_out(const float* __restrict__ Wout,
                                             float* __restrict__ out) {
    __shared__ float s_w[32 * 256];
    __shared__ float s_ns[16 * 64];
    const int tid = threadIdx.x;
    const int node0 = blockIdx.x * 16;
#pragma unroll
    for (int r = 0; r < 4; r++) {
        int lin = tid + r * 256; int t = lin >> 6, i = lin & 63;
        s_ns[t * 64 + i] = g_ns[(size_t)(node0 + t) * 64 + i];
    }
    float acc[16];
#pragma unroll
    for (int t = 0; t < 16; t++) acc[t] = 0.f;
    for (int ic = 0; ic < 2; ic++) {
        __syncthreads();
        const float4* wg = (const float4*)(Wout + (size_t)ic * 32 * 256);
        float4* ws4 = (float4*)s_w;
#pragma unroll
        for (int r = 0; r < 8; r++) ws4[tid + r * 256] = wg[tid + r * 256];
        __syncthreads();
#pragma unroll 8
        for (int i = 0; i < 32; i++) {
            float w = s_w[i * 256 + tid];
#pragma unroll
            for (int t = 0; t < 16; t++) acc[t] += s_ns[t * 64 + ic * 32 + i] * w;
        }
    }
#pragma unroll
    for (int t = 0; t < 16; t++)
        out[(size_t)(node0 + t) * 256 + tid] = acc[t] * INV8;
}

// =====================================================================================
extern "C" void kernel_launch(void* const* d_in, const int* in_sizes, int n_in,
                              void* d_out, int out_size) {
    const float* x    = (const float*)d_in[0];
    const float* eattr= (const float*)d_in[1];
    const float* Win  = (const float*)d_in[2];
    const float* Wout = (const float*)d_in[3];
    const float* Wss  = (const float*)d_in[4];
    const float* Wvv0 = (const float*)d_in[5];
    const float* Wsv  = (const float*)d_in[6];
    const float* Wvs  = (const float*)d_in[7];
    const float* gmw  = (const float*)d_in[8];
    const float* gmb  = (const float*)d_in[9];
    const float* Wuss = (const float*)d_in[10];
    const float* Wuvv = (const float*)d_in[11];
    const float* Wusv = (const float*)d_in[12];
    const float* Wuvs = (const float*)d_in[13];
    const float* guw  = (const float*)d_in[14];
    const float* gub  = (const float*)d_in[15];
    const int*   eidx = (const int*)d_in[16];
    float* out = (float*)d_out;

    void *p_nv = 0, *p_as = 0, *p_av = 0;
    cudaGetSymbolAddress(&p_nv, g_nv);
    cudaGetSymbolAddress(&p_as, g_as);
    cudaGetSymbolAddress(&p_av, g_av);

    cudaFuncSetAttribute(k_bilin, cudaFuncAttributeMaxDynamicSharedMemorySize, BILIN_SMEM);

    cudaMemsetAsync(p_nv, 0, sizeof(float) * NN * 96, 0);
    k_in<<<NN / 32, 256>>>(x, Win);

    for (int l = 0; l < 2; l++) {
        k_feat<<<NN / 8, 256>>>(Wss + l * 4096, Wvv0 + l * 2048,
                                Wsv + l * 2048, Wvs + l * 1024);
        cudaMemsetAsync(p_as, 0, sizeof(float) * NN * 64, 0);
        cudaMemsetAsync(p_av, 0, sizeof(float) * NN * 96, 0);
        k_edge<<<EE / 8, 256>>>(eattr, eidx, gmw + l * 96, gmb + l * 96);
        k_bilin<<<NN / 32, 256, BILIN_SMEM>>>(Wuss + (size_t)l * 262144,
                                              Wuvv + (size_t)l * 65536,
                                              Wusv + (size_t)l * 65536,
                                              Wuvs + (size_t)l * 65536,
                                              guw + l * 96, gub + l * 96);
    }
    k_out<<<NN / 16, 256>>>(Wout, out);
}